// round 16
// baseline (speedup 1.0000x reference)
#include <cuda_runtime.h>
#include <cuda.h>
#include <cuda_bf16.h>
#include <math.h>

#define Bsz 16384
#define Dd  1024
#define Rr  64
#define Ee  4
#define Ll  3
#define ER  256

typedef unsigned u32;
typedef unsigned long long u64;
typedef __nv_bfloat16 bf16;

#if defined(__CUDA_ARCH_FEAT_SM103_ALL) || defined(__CUDA_ARCH_FEAT_SM100_ALL) || \
    defined(__CUDA_ARCH_FAMILY_SPECIFIC__) || defined(__CUDA_ARCH_SPECIFIC__)
#define TC_OK 1
#else
#define TC_OK 0
#endif

// ---------------- scratch ----------------
#define VSEG (ER * 3 * Dd)
#define USEG (Dd * 3 * ER)
__device__ float g_xl [Bsz * Dd];
__device__ bf16  g_xh [Bsz * Dd];
__device__ bf16  g_xlo[Bsz * Dd];
__device__ float g_t1 [Bsz * ER];
__device__ bf16  g_sh [Bsz * ER];
__device__ bf16  g_sl [Bsz * ER];
__device__ bf16  g_V2 [Ll * VSEG];   // per layer [256][3072] = [Vhi,Vlo,Vhi]
__device__ bf16  g_U2 [Ll * USEG];   // per layer [1024][768] = [Uhi,Ulo,Uhi]

// ---------------- PTX helpers ----------------
__device__ __forceinline__ u32 smem_u32(const void* p) {
    u32 a;
    asm("{ .reg .u64 t; cvta.to.shared.u64 t, %1; cvt.u32.u64 %0, t; }" : "=r"(a) : "l"(p));
    return a;
}
#define TC_ALLOC(sa, n)   asm volatile("tcgen05.alloc.cta_group::1.sync.aligned.shared::cta.b32 [%0], %1;" :: "r"(sa), "r"((u32)(n)) : "memory")
#define TC_DEALLOC(t, n)  asm volatile("tcgen05.dealloc.cta_group::1.sync.aligned.b32 %0, %1;" :: "r"(t), "r"((u32)(n)))
#define TC_COMMIT(mb)     asm volatile("tcgen05.commit.cta_group::1.mbarrier::arrive::one.shared::cluster.b64 [%0];" :: "r"(mb) : "memory")
#define TC_FENCE_AFTER()  asm volatile("tcgen05.fence::after_thread_sync;" ::: "memory")
#define TC_WAIT_LD()      asm volatile("tcgen05.wait::ld.sync.aligned;" ::: "memory")
#define FENCE_ASYNC()     asm volatile("fence.proxy.async.shared::cta;" ::: "memory")
#define MBAR_INIT(mb, c)  asm volatile("mbarrier.init.shared.b64 [%0], %1;" :: "r"(mb), "r"((u32)(c)) : "memory")
#define MBAR_EXPECT_TX(mb, n) asm volatile("mbarrier.arrive.expect_tx.shared.b64 _, [%0], %1;" :: "r"(mb), "r"((u32)(n)) : "memory")
#define MBAR_ARRIVE(mb)   asm volatile("mbarrier.arrive.shared.b64 _, [%0];" :: "r"(mb) : "memory")

#if TC_OK
#define TMA2D(smem, map, x, y, mbar) \
    asm volatile("cp.async.bulk.tensor.2d.shared::cta.global.tile.mbarrier::complete_tx::bytes " \
        "[%0], [%1, {%2, %3}], [%4];" \
        :: "r"((u32)(smem)), "l"(map), "r"((int)(x)), "r"((int)(y)), "r"((u32)(mbar)) : "memory")
#define TMA3D(smem, map, x, y, z, mbar) \
    asm volatile("cp.async.bulk.tensor.3d.shared::cta.global.tile.mbarrier::complete_tx::bytes " \
        "[%0], [%1, {%2, %3, %4}], [%5];" \
        :: "r"((u32)(smem)), "l"(map), "r"((int)(x)), "r"((int)(y)), "r"((int)(z)), "r"((u32)(mbar)) : "memory")
#endif

__device__ __forceinline__ void mbar_wait(u32 mb, u32 parity) {
    asm volatile(
        "{\n\t.reg .pred P1;\n\t"
        "WAIT_LOOP_%=:\n\t"
        "mbarrier.try_wait.parity.acquire.cta.shared::cta.b64 P1, [%0], %1, 0x989680;\n\t"
        "@P1 bra.uni WAIT_DONE_%=;\n\t"
        "bra.uni WAIT_LOOP_%=;\n\t"
        "WAIT_DONE_%=:\n\t}"
        :: "r"(mb), "r"(parity) : "memory");
}
__device__ __forceinline__ void mma_f16_ss(u32 d, u64 ad, u64 bd, u32 idesc, u32 accum) {
#if TC_OK
    asm volatile(
        "{\n\t.reg .pred p;\n\tsetp.ne.u32 p, %4, 0;\n\t"
        "tcgen05.mma.cta_group::1.kind::f16 [%0], %1, %2, %3, {%5,%5,%5,%5}, p;\n\t}"
        :: "r"(d), "l"(ad), "l"(bd), "r"(idesc), "r"(accum), "r"(0u) : "memory");
#endif
}
#define LDTM32(r, a) \
    asm volatile("tcgen05.ld.sync.aligned.32x32b.x32.b32 " \
        "{%0,%1,%2,%3,%4,%5,%6,%7,%8,%9,%10,%11,%12,%13,%14,%15," \
        "%16,%17,%18,%19,%20,%21,%22,%23,%24,%25,%26,%27,%28,%29,%30,%31}, [%32];" \
        : "=r"((r)[0]),"=r"((r)[1]),"=r"((r)[2]),"=r"((r)[3]),"=r"((r)[4]),"=r"((r)[5]),"=r"((r)[6]),"=r"((r)[7]), \
          "=r"((r)[8]),"=r"((r)[9]),"=r"((r)[10]),"=r"((r)[11]),"=r"((r)[12]),"=r"((r)[13]),"=r"((r)[14]),"=r"((r)[15]), \
          "=r"((r)[16]),"=r"((r)[17]),"=r"((r)[18]),"=r"((r)[19]),"=r"((r)[20]),"=r"((r)[21]),"=r"((r)[22]),"=r"((r)[23]), \
          "=r"((r)[24]),"=r"((r)[25]),"=r"((r)[26]),"=r"((r)[27]),"=r"((r)[28]),"=r"((r)[29]),"=r"((r)[30]),"=r"((r)[31]) \
        : "r"(a))

__device__ __forceinline__ u64 smem_desc(u32 addr) {
    const u64 base = (u64(2) << 61) | (u64(1) << 46) | (u64(64) << 32) | (u64(1) << 16);
    return base | ((u64)(addr >> 4) & 0x3FFF);
}
__device__ __forceinline__ u32 sw128(u32 off) { return off ^ ((off >> 3) & 0x70); }

#define IDESC_256 ((1u<<4) | (1u<<7) | (1u<<10) | ((256u/8)<<17) | ((128u/16)<<24))

// gemm1 smem (4 stages, round-15): full mbars @16..79; done @80..143;
// A(s) @1024 (16KB); B(s) @66560 (32KB). total 198656.
#define MB_FULL(s) (16 + (s) * 16)
#define MB_DONE(s) (80 + (s) * 16)
#define SM_A(s)  (1024 + (s) * 16384)
#define SM_B(s)  (66560 + (s) * 32768)
#define SM_TOTAL 198656
#define STAGE_BYTES 49152u

// gemm2 smem (persistent, N=256 subtiles, 2 k-stages):
// k-full @16/32, k-done @48/64, acc_ready(b) @80/96, buf_free(b) @112/128;
// A(s) @1024 (16KB ea), B(s) @33792 (32KB ea), transpose @99328 (33KB).
#define G2F(s)   (16 + (s) * 16)
#define G2D(s)   (48 + (s) * 16)
#define G2ACC(b) (80 + (b) * 16)
#define G2FREE(b) (112 + (b) * 16)
#define G2_A(s)  (1024 + (s) * 16384)
#define G2_B(s)  (33792 + (s) * 32768)
#define G2_T     99328
#define SM2_TOTAL 133120
#define STAGE2_BYTES 49152u

// ---------------------------------------------------------------------------
// prep kernels
// ---------------------------------------------------------------------------
__global__ void conv_x(const float* __restrict__ x) {
    int i = (blockIdx.x * 256 + threadIdx.x) * 4;
    float4 v = *(const float4*)(x + i);
    float f[4] = {v.x, v.y, v.z, v.w};
    #pragma unroll
    for (int k = 0; k < 4; k++) {
        bf16 h = __float2bfloat16(f[k]);
        g_xh[i + k]  = h;
        g_xlo[i + k] = __float2bfloat16(f[k] - __bfloat162float(h));
    }
}
__global__ void pack_V(const float* __restrict__ V) {
    int idx = blockIdx.x * 256 + threadIdx.x;
    int l = idx / VSEG, r = idx % VSEG;
    int n = r / 3072, kk = r % 3072;
    int seg = kk >> 10, k = kk & 1023;
    float v = V[(size_t)l * (Ee * Rr * Dd) + n * 1024 + k];
    bf16 h = __float2bfloat16(v);
    g_V2[idx] = (seg == 1) ? __float2bfloat16(v - __bfloat162float(h)) : h;
}
__global__ void pack_U(const float* __restrict__ U) {
    int idx = blockIdx.x * 256 + threadIdx.x;
    int l = idx / USEG, r = idx % USEG;
    int n = r / 768, kk = r % 768;
    int seg = kk >> 8, k = kk & 255;
    int e = k >> 6, rr = k & 63;
    float v = U[(size_t)l * (Ee * Rr * Dd) + e * (Dd * Rr) + n * Rr + rr];
    bf16 h = __float2bfloat16(v);
    g_U2[idx] = (seg == 1) ? __float2bfloat16(v - __bfloat162float(h)) : h;
}

// ---------------------------------------------------------------------------
// GEMM1 (round-15 verbatim): 4-stage TMA, tile 128x256, grid 128
// ---------------------------------------------------------------------------
__global__ void __launch_bounds__(256, 1)
gemm1_tc(const __grid_constant__ CUtensorMap mAh,
         const __grid_constant__ CUtensorMap mAl,
         const __grid_constant__ CUtensorMap mB,
         int layer) {
#if TC_OK
    extern __shared__ char smem[];
    const u32 sb = smem_u32(smem);
    const int tid = threadIdx.x, wid = tid >> 5, lane = tid & 31;
    const int m0 = blockIdx.x * 128;
    const int T = 48;

    if (wid == 0) TC_ALLOC(sb, 256);
    if (tid == 0) {
        #pragma unroll
        for (int s = 0; s < 4; s++) { MBAR_INIT(sb + MB_FULL(s), 1); MBAR_INIT(sb + MB_DONE(s), 1); }
        FENCE_ASYNC();
    }
    __syncthreads();
    u32 tmem;
    asm volatile("ld.shared.b32 %0, [%1];" : "=r"(tmem) : "r"(sb));

    if (tid == 0) {
        u32 fullph[4] = {0, 0, 0, 0}, doneph[4] = {0, 0, 0, 0};
        auto issue_load = [&](int t, int s) {
            MBAR_EXPECT_TX(sb + MB_FULL(s), STAGE_BYTES);
            const CUtensorMap* am = ((t >> 4) < 2) ? &mAh : &mAl;
            TMA2D(sb + SM_A(s), am, (t & 15) << 6, m0, sb + MB_FULL(s));
            TMA3D(sb + SM_B(s), &mB, t << 6, 0, layer, sb + MB_FULL(s));
        };
        issue_load(0, 0); issue_load(1, 1); issue_load(2, 2);

        #pragma unroll 1
        for (int t = 0; t < T; t++) {
            const int s = t & 3;
            mbar_wait(sb + MB_FULL(s), fullph[s]); fullph[s] ^= 1;
            u64 ad = smem_desc(sb + SM_A(s));
            u64 bd = smem_desc(sb + SM_B(s));
            #pragma unroll
            for (int k = 0; k < 4; k++)
                mma_f16_ss(tmem, ad + k * 2, bd + k * 2, IDESC_256, (t > 0) || (k > 0));
            TC_COMMIT(sb + MB_DONE(s));
            const int nt = t + 3;
            if (nt < T) {
                const int sl = nt & 3;
                if (t >= 1) { mbar_wait(sb + MB_DONE(sl), doneph[sl]); doneph[sl] ^= 1; }
                issue_load(nt, sl);
            }
        }
        #pragma unroll
        for (int s = 0; s < 4; s++) mbar_wait(sb + MB_DONE(s), doneph[s]);
    }
    __syncthreads();
    TC_FENCE_AFTER();

    const int sp = wid & 3;
    const int cbase = (wid >> 2) * 128;
    float* Tb = (float*)(smem + 1024) + wid * 1056;
    #pragma unroll 1
    for (int j = 0; j < 4; j++) {
        const int cb = cbase + j * 32;
        u32 r[32];
        LDTM32(r, tmem + cb);
        TC_WAIT_LD();
        #pragma unroll
        for (int c = 0; c < 32; c++) Tb[lane * 33 + c] = tanhf(__uint_as_float(r[c]));
        __syncwarp();
        #pragma unroll
        for (int rr = 0; rr < 32; rr++)
            g_t1[(size_t)(m0 + sp * 32 + rr) * ER + cb + lane] = Tb[rr * 33 + lane];
        __syncwarp();
    }
    __syncthreads();
    if (wid == 0) TC_DEALLOC(tmem, 256);
#else
    const int tid = threadIdx.x;
    const int m0 = blockIdx.x * 128;
    const bf16* Vb = g_V2 + (size_t)layer * VSEG;
    for (int o = tid; o < 128 * 256; o += 256) {
        int row = o >> 8, col = o & 255;
        const bf16* xh = g_xh  + (size_t)(m0 + row) * Dd;
        const bf16* xo = g_xlo + (size_t)(m0 + row) * Dd;
        const bf16* bv = Vb + (size_t)col * 3072;
        float acc = 0.f;
        for (int k = 0; k < Dd; k++) {
            float bh = __bfloat162float(bv[k]);
            float bl = __bfloat162float(bv[1024 + k]);
            acc += __bfloat162float(xh[k]) * (bh + bl) + __bfloat162float(xo[k]) * bh;
        }
        g_t1[(size_t)(m0 + row) * ER + col] = tanhf(acc);
    }
#endif
}

// ---------------------------------------------------------------------------
// gate_mix (round-10 verbatim)
// ---------------------------------------------------------------------------
#define CSTR 65
__global__ __launch_bounds__(256)
void gate_mix(const float* __restrict__ xl,
              const float* __restrict__ Cw,
              const float* __restrict__ gw)
{
    extern __shared__ float sm[];
    float* Cs  = sm;
    float* t1s = sm + 4 * Rr * CSTR;

    const int tid = threadIdx.x;
    for (int idx = tid; idx < Ee * Rr * Rr; idx += 256) {
        int e = idx >> 12, rem = idx & 4095, r = rem >> 6, s = rem & 63;
        Cs[(e * Rr + r) * CSTR + s] = Cw[idx];
    }
    const int b0 = blockIdx.x << 5;
    for (int idx = tid; idx < 32 * 256; idx += 256) {
        int rl = idx >> 8, j = idx & 255;
        t1s[idx] = g_t1[(size_t)(b0 + rl) * ER + j];
    }
    __syncthreads();

    const int w = tid >> 5, lane = tid & 31;
    #pragma unroll 1
    for (int q = 0; q < 4; q++) {
        const int rl = (w << 2) + q;
        const int b = b0 + rl;
        const float* xr = xl + (size_t)b * Dd;

        float s0 = 0.f, s1 = 0.f, s2 = 0.f, s3 = 0.f;
        for (int d = lane; d < Dd; d += 32) {
            float xv = xr[d];
            s0 = fmaf(xv, gw[d],          s0);
            s1 = fmaf(xv, gw[Dd + d],     s1);
            s2 = fmaf(xv, gw[2 * Dd + d], s2);
            s3 = fmaf(xv, gw[3 * Dd + d], s3);
        }
        #pragma unroll
        for (int o = 16; o; o >>= 1) {
            s0 += __shfl_xor_sync(0xffffffffu, s0, o);
            s1 += __shfl_xor_sync(0xffffffffu, s1, o);
            s2 += __shfl_xor_sync(0xffffffffu, s2, o);
            s3 += __shfl_xor_sync(0xffffffffu, s3, o);
        }
        float mx = fmaxf(fmaxf(s0, s1), fmaxf(s2, s3));
        float e0 = expf(s0 - mx), e1 = expf(s1 - mx), e2 = expf(s2 - mx), e3 = expf(s3 - mx);
        float inv = 1.f / (e0 + e1 + e2 + e3);
        float gg[4] = { e0 * inv, e1 * inv, e2 * inv, e3 * inv };

        const float* t1r = t1s + rl * ER;
        #pragma unroll
        for (int i = 0; i < 8; i++) {
            int j = (i << 5) + lane;
            int e = j >> 6, r = j & 63;
            const float* cr = Cs + (e * Rr + r) * CSTR;
            const float* tv = t1r + (e << 6);
            float sum = 0.f;
            #pragma unroll
            for (int s = 0; s < 64; s++) sum = fmaf(cr[s], tv[s], sum);
            float val = gg[e] * tanhf(sum);
            bf16 h = __float2bfloat16(val);
            size_t o = (size_t)b * ER + j;
            g_sh[o] = h;
            g_sl[o] = __float2bfloat16(val - __bfloat162float(h));
        }
    }
}

// ---------------------------------------------------------------------------
// GEMM2 v2: persistent per-m-block CTA, 4 N=256 subtiles, TMEM ping-pong.
// Warp 8 (thread 256) drives TMA+MMA continuously over 48 k-tiles; warps 0-7
// run the epilogue on the other accumulator buffer concurrently.
// ---------------------------------------------------------------------------
__global__ void __launch_bounds__(288, 1)
gemm2_tc(const __grid_constant__ CUtensorMap mSh,
         const __grid_constant__ CUtensorMap mSl,
         const __grid_constant__ CUtensorMap mU,
         const float* __restrict__ xl_in,
         const float* __restrict__ x0,
         const float* __restrict__ bias,
         float* __restrict__ out,
         int write_next, int layer)
{
#if TC_OK
    extern __shared__ char smem[];
    const u32 sb = smem_u32(smem);
    const int tid = threadIdx.x, wid = tid >> 5, lane = tid & 31;
    const int m0 = blockIdx.x * 128;

    if (wid == 0) TC_ALLOC(sb, 512);
    if (tid == 0) {
        #pragma unroll
        for (int s = 0; s < 2; s++) {
            MBAR_INIT(sb + G2F(s), 1); MBAR_INIT(sb + G2D(s), 1);
            MBAR_INIT(sb + G2ACC(s), 1); MBAR_INIT(sb + G2FREE(s), 8);
        }
        FENCE_ASYNC();
    }
    __syncthreads();
    u32 tmem;
    asm volatile("ld.shared.b32 %0, [%1];" : "=r"(tmem) : "r"(sb));

    if (tid == 256) {
        // ---- driver: 48 continuous k-tiles (4 subtiles x 12) ----
        u32 fph[2] = {0, 0}, dph[2] = {0, 0}, fbph[2] = {0, 0};
        auto issue_load = [&](int kt, int s) {
            const int nt = kt / 12, t = kt - nt * 12;
            MBAR_EXPECT_TX(sb + G2F(s), STAGE2_BYTES);
            const CUtensorMap* am = ((t >> 2) < 2) ? &mSh : &mSl;
            TMA2D(sb + G2_A(s), am, (t & 3) << 6, m0, sb + G2F(s));
            TMA3D(sb + G2_B(s), &mU, t << 6, nt * 256, layer, sb + G2F(s));
        };
        issue_load(0, 0); issue_load(1, 1);

        #pragma unroll 1
        for (int kt = 0; kt < 48; kt++) {
            const int s = kt & 1;
            const int nt = kt / 12, t = kt - nt * 12;
            const int b = nt & 1;
            if (t == 0 && nt >= 2) { mbar_wait(sb + G2FREE(b), fbph[b]); fbph[b] ^= 1; }
            mbar_wait(sb + G2F(s), fph[s]); fph[s] ^= 1;
            u64 ad = smem_desc(sb + G2_A(s));
            u64 bd = smem_desc(sb + G2_B(s));
            const u32 dtm = tmem + b * 256;
            #pragma unroll
            for (int k = 0; k < 4; k++)
                mma_f16_ss(dtm, ad + k * 2, bd + k * 2, IDESC_256, (t > 0) || (k > 0));
            TC_COMMIT(sb + G2D(s));
            if (t == 11) TC_COMMIT(sb + G2ACC(b));   // fires when subtile's MMAs drain
            const int nk = kt + 2;
            if (nk < 48) {
                mbar_wait(sb + G2D(s), dph[s]); dph[s] ^= 1;
                issue_load(nk, s);
            }
        }
    } else if (wid < 8) {
        // ---- epilogue warps: process subtile nt on buffer nt&1 ----
        u32 aph[2] = {0, 0};
        const int sp = wid & 3;
        const int cbase = (wid >> 2) * 128;
        float* Tb = (float*)(smem + G2_T) + wid * 1056;
        #pragma unroll 1
        for (int nt = 0; nt < 4; nt++) {
            const int b = nt & 1;
            mbar_wait(sb + G2ACC(b), aph[b]); aph[b] ^= 1;
            TC_FENCE_AFTER();
            const int n0 = nt * 256;
            #pragma unroll 1
            for (int j = 0; j < 4; j++) {
                const int cb = cbase + j * 32;
                u32 r[32];
                LDTM32(r, tmem + b * 256 + cb);
                const int col = n0 + cb + lane;
                const float bv = bias[col];
                float xv[32], x0v[32];
                #pragma unroll
                for (int rr = 0; rr < 32; rr++) {
                    const size_t idx = (size_t)(m0 + sp * 32 + rr) * Dd + col;
                    xv[rr]  = xl_in[idx];
                    x0v[rr] = x0[idx];
                }
                TC_WAIT_LD();
                #pragma unroll
                for (int c = 0; c < 32; c++) Tb[lane * 33 + c] = __uint_as_float(r[c]);
                __syncwarp();
                if (write_next) {
                    #pragma unroll
                    for (int rr = 0; rr < 32; rr++) {
                        const size_t idx = (size_t)(m0 + sp * 32 + rr) * Dd + col;
                        float o = fmaf(x0v[rr], bv + Tb[rr * 33 + lane], xv[rr]);
                        out[idx] = o;
                        bf16 h = __float2bfloat16(o);
                        g_xh[idx]  = h;
                        g_xlo[idx] = __float2bfloat16(o - __bfloat162float(h));
                    }
                } else {
                    #pragma unroll
                    for (int rr = 0; rr < 32; rr++) {
                        const size_t idx = (size_t)(m0 + sp * 32 + rr) * Dd + col;
                        out[idx] = fmaf(x0v[rr], bv + Tb[rr * 33 + lane], xv[rr]);
                    }
                }
                __syncwarp();
            }
            if (lane == 0) MBAR_ARRIVE(sb + G2FREE(b));
        }
    }
    __syncthreads();
    if (wid == 0) TC_DEALLOC(tmem, 512);
#else
    const int tid = threadIdx.x;
    const int m0 = blockIdx.x * 128;
    const bf16* Ub = g_U2 + (size_t)layer * USEG;
    for (int o = tid; o < 128 * 1024; o += 288) {
        int row = o >> 10, col = o & 1023;
        const bf16* sh = g_sh + (size_t)(m0 + row) * ER;
        const bf16* sl = g_sl + (size_t)(m0 + row) * ER;
        const bf16* uv = Ub + (size_t)col * 768;
        float acc = 0.f;
        for (int k = 0; k < ER; k++) {
            float uh = __bfloat162float(uv[k]);
            float ul = __bfloat162float(uv[256 + k]);
            acc += __bfloat162float(sh[k]) * (uh + ul) + __bfloat162float(sl[k]) * uh;
        }
        const size_t idx = (size_t)(m0 + row) * Dd + col;
        float ov = fmaf(x0[idx], bias[col] + acc, xl_in[idx]);
        out[idx] = ov;
        if (write_next) {
            bf16 h = __float2bfloat16(ov);
            g_xh[idx]  = h;
            g_xlo[idx] = __float2bfloat16(ov - __bfloat162float(h));
        }
    }
#endif
}

// ---------------------------------------------------------------------------
// Launch
// ---------------------------------------------------------------------------
typedef CUresult (CUDAAPI *PFN_encodeTiled)(
    CUtensorMap*, CUtensorMapDataType, cuuint32_t, void*,
    const cuuint64_t*, const cuuint64_t*, const cuuint32_t*, const cuuint32_t*,
    CUtensorMapInterleave, CUtensorMapSwizzle, CUtensorMapL2promotion, CUtensorMapFloatOOBfill);

extern "C" void kernel_launch(void* const* d_in, const int* in_sizes, int n_in,
                              void* d_out, int out_size)
{
    const float* x    = (const float*)d_in[0];
    const float* U    = (const float*)d_in[1];
    const float* V    = (const float*)d_in[2];
    const float* C    = (const float*)d_in[3];
    const float* bias = (const float*)d_in[4];
    const float* gw   = (const float*)d_in[5];
    float* out = (float*)d_out;

    float* p_xl = nullptr;
    cudaGetSymbolAddress((void**)&p_xl, g_xl);
    void *p_xh, *p_xlo, *p_sh, *p_sl, *p_V2, *p_U2;
    cudaGetSymbolAddress(&p_xh,  g_xh);
    cudaGetSymbolAddress(&p_xlo, g_xlo);
    cudaGetSymbolAddress(&p_sh,  g_sh);
    cudaGetSymbolAddress(&p_sl,  g_sl);
    cudaGetSymbolAddress(&p_V2,  g_V2);
    cudaGetSymbolAddress(&p_U2,  g_U2);

    static PFN_encodeTiled enc = nullptr;
    if (!enc) {
        cudaDriverEntryPointQueryResult st;
        cudaGetDriverEntryPoint("cuTensorMapEncodeTiled", (void**)&enc,
                                cudaEnableDefault, &st);
    }

    auto enc2d = [&](CUtensorMap* m, void* base, unsigned long long d0,
                     unsigned long long d1, unsigned b0, unsigned b1) {
        cuuint64_t dims[2] = {d0, d1};
        cuuint64_t strides[1] = {d0 * 2};
        cuuint32_t box[2] = {b0, b1};
        cuuint32_t es[2] = {1, 1};
        enc(m, CU_TENSOR_MAP_DATA_TYPE_BFLOAT16, 2, base, dims, strides, box, es,
            CU_TENSOR_MAP_INTERLEAVE_NONE, CU_TENSOR_MAP_SWIZZLE_128B,
            CU_TENSOR_MAP_L2_PROMOTION_L2_128B, CU_TENSOR_MAP_FLOAT_OOB_FILL_NONE);
    };
    auto enc3d = [&](CUtensorMap* m, void* base, unsigned long long d0,
                     unsigned long long d1, unsigned long long d2,
                     unsigned b0, unsigned b1) {
        cuuint64_t dims[3] = {d0, d1, d2};
        cuuint64_t strides[2] = {d0 * 2, d0 * d1 * 2};
        cuuint32_t box[3] = {b0, b1, 1};
        cuuint32_t es[3] = {1, 1, 1};
        enc(m, CU_TENSOR_MAP_DATA_TYPE_BFLOAT16, 3, base, dims, strides, box, es,
            CU_TENSOR_MAP_INTERLEAVE_NONE, CU_TENSOR_MAP_SWIZZLE_128B,
            CU_TENSOR_MAP_L2_PROMOTION_L2_128B, CU_TENSOR_MAP_FLOAT_OOB_FILL_NONE);
    };

    CUtensorMap mAh{}, mAl{}, mV{}, mSh{}, mSl{}, mU{};
    enc2d(&mAh, p_xh,  1024, 16384, 64, 128);
    enc2d(&mAl, p_xlo, 1024, 16384, 64, 128);
    enc3d(&mV,  p_V2,  3072, 256, 3, 64, 256);
    enc2d(&mSh, p_sh,  256, 16384, 64, 128);
    enc2d(&mSl, p_sl,  256, 16384, 64, 128);
    enc3d(&mU,  p_U2,  768, 1024, 3, 64, 256);

    const int smem_gate = (4 * Rr * CSTR + 32 * 256) * (int)sizeof(float); // 99328
    cudaFuncSetAttribute(gate_mix, cudaFuncAttributeMaxDynamicSharedMemorySize, smem_gate);
    cudaFuncSetAttribute(gemm1_tc, cudaFuncAttributeMaxDynamicSharedMemorySize, SM_TOTAL);
    cudaFuncSetAttribute(gemm2_tc, cudaFuncAttributeMaxDynamicSharedMemorySize, SM2_TOTAL);

    conv_x<<<Bsz * Dd / 1024, 256>>>(x);
    pack_V<<<Ll * VSEG / 256, 256>>>(V);
    pack_U<<<Ll * USEG / 256, 256>>>(U);

    for (int l = 0; l < Ll; l++) {
        const float* xin  = (l == 0)      ? x   : p_xl;
        float*       xout = (l == Ll - 1) ? out : p_xl;
        gemm1_tc<<<Bsz / 128, 256, SM_TOTAL>>>(mAh, mAl, mV, l);
        gate_mix<<<Bsz / 32, 256, smem_gate>>>(xin, C + (size_t)l * Ee * Rr * Rr, gw);
        gemm2_tc<<<Bsz / 128, 288, SM2_TOTAL>>>(mSh, mSl, mU, xin, x,
                                                bias + (size_t)l * Dd, xout,
                                                (l < Ll - 1) ? 1 : 0, l);
    }
}

// round 17
// speedup vs baseline: 1.0323x; 1.0323x over previous
#include <cuda_runtime.h>
#include <cuda.h>
#include <cuda_bf16.h>
#include <math.h>

#define Bsz 16384
#define Dd  1024
#define Rr  64
#define Ee  4
#define Ll  3
#define ER  256

typedef unsigned u32;
typedef unsigned long long u64;
typedef __nv_bfloat16 bf16;

#if defined(__CUDA_ARCH_FEAT_SM103_ALL) || defined(__CUDA_ARCH_FEAT_SM100_ALL) || \
    defined(__CUDA_ARCH_FAMILY_SPECIFIC__) || defined(__CUDA_ARCH_SPECIFIC__)
#define TC_OK 1
#else
#define TC_OK 0
#endif

// ---------------- scratch ----------------
#define VSEG (ER * 3 * Dd)
#define USEG (Dd * 3 * ER)
__device__ float g_xl [Bsz * Dd];
__device__ bf16  g_xh [Bsz * Dd];
__device__ bf16  g_xlo[Bsz * Dd];
__device__ float g_t1 [Bsz * ER];
__device__ bf16  g_sh [Bsz * ER];
__device__ bf16  g_sl [Bsz * ER];
__device__ bf16  g_V2 [Ll * VSEG];   // per layer [256][3072] = [Vhi,Vlo,Vhi]
__device__ bf16  g_U2 [Ll * USEG];   // per layer [1024][768] = [Uhi,Ulo,Uhi]

// ---------------- PTX helpers ----------------
__device__ __forceinline__ u32 smem_u32(const void* p) {
    u32 a;
    asm("{ .reg .u64 t; cvta.to.shared.u64 t, %1; cvt.u32.u64 %0, t; }" : "=r"(a) : "l"(p));
    return a;
}
#define TC_ALLOC(sa, n)   asm volatile("tcgen05.alloc.cta_group::1.sync.aligned.shared::cta.b32 [%0], %1;" :: "r"(sa), "r"((u32)(n)) : "memory")
#define TC_DEALLOC(t, n)  asm volatile("tcgen05.dealloc.cta_group::1.sync.aligned.b32 %0, %1;" :: "r"(t), "r"((u32)(n)))
#define TC_COMMIT(mb)     asm volatile("tcgen05.commit.cta_group::1.mbarrier::arrive::one.shared::cluster.b64 [%0];" :: "r"(mb) : "memory")
#define TC_FENCE_AFTER()  asm volatile("tcgen05.fence::after_thread_sync;" ::: "memory")
#define TC_WAIT_LD()      asm volatile("tcgen05.wait::ld.sync.aligned;" ::: "memory")
#define FENCE_ASYNC()     asm volatile("fence.proxy.async.shared::cta;" ::: "memory")
#define MBAR_INIT(mb, c)  asm volatile("mbarrier.init.shared.b64 [%0], %1;" :: "r"(mb), "r"((u32)(c)) : "memory")
#define MBAR_EXPECT_TX(mb, n) asm volatile("mbarrier.arrive.expect_tx.shared.b64 _, [%0], %1;" :: "r"(mb), "r"((u32)(n)) : "memory")

#if TC_OK
#define TMA2D(smem, map, x, y, mbar) \
    asm volatile("cp.async.bulk.tensor.2d.shared::cta.global.tile.mbarrier::complete_tx::bytes " \
        "[%0], [%1, {%2, %3}], [%4];" \
        :: "r"((u32)(smem)), "l"(map), "r"((int)(x)), "r"((int)(y)), "r"((u32)(mbar)) : "memory")
#define TMA3D(smem, map, x, y, z, mbar) \
    asm volatile("cp.async.bulk.tensor.3d.shared::cta.global.tile.mbarrier::complete_tx::bytes " \
        "[%0], [%1, {%2, %3, %4}], [%5];" \
        :: "r"((u32)(smem)), "l"(map), "r"((int)(x)), "r"((int)(y)), "r"((int)(z)), "r"((u32)(mbar)) : "memory")
#endif

__device__ __forceinline__ void mbar_wait(u32 mb, u32 parity) {
    asm volatile(
        "{\n\t.reg .pred P1;\n\t"
        "WAIT_LOOP_%=:\n\t"
        "mbarrier.try_wait.parity.acquire.cta.shared::cta.b64 P1, [%0], %1, 0x989680;\n\t"
        "@P1 bra.uni WAIT_DONE_%=;\n\t"
        "bra.uni WAIT_LOOP_%=;\n\t"
        "WAIT_DONE_%=:\n\t}"
        :: "r"(mb), "r"(parity) : "memory");
}
__device__ __forceinline__ void mma_f16_ss(u32 d, u64 ad, u64 bd, u32 idesc, u32 accum) {
#if TC_OK
    asm volatile(
        "{\n\t.reg .pred p;\n\tsetp.ne.u32 p, %4, 0;\n\t"
        "tcgen05.mma.cta_group::1.kind::f16 [%0], %1, %2, %3, {%5,%5,%5,%5}, p;\n\t}"
        :: "r"(d), "l"(ad), "l"(bd), "r"(idesc), "r"(accum), "r"(0u) : "memory");
#endif
}
#define LDTM32(r, a) \
    asm volatile("tcgen05.ld.sync.aligned.32x32b.x32.b32 " \
        "{%0,%1,%2,%3,%4,%5,%6,%7,%8,%9,%10,%11,%12,%13,%14,%15," \
        "%16,%17,%18,%19,%20,%21,%22,%23,%24,%25,%26,%27,%28,%29,%30,%31}, [%32];" \
        : "=r"((r)[0]),"=r"((r)[1]),"=r"((r)[2]),"=r"((r)[3]),"=r"((r)[4]),"=r"((r)[5]),"=r"((r)[6]),"=r"((r)[7]), \
          "=r"((r)[8]),"=r"((r)[9]),"=r"((r)[10]),"=r"((r)[11]),"=r"((r)[12]),"=r"((r)[13]),"=r"((r)[14]),"=r"((r)[15]), \
          "=r"((r)[16]),"=r"((r)[17]),"=r"((r)[18]),"=r"((r)[19]),"=r"((r)[20]),"=r"((r)[21]),"=r"((r)[22]),"=r"((r)[23]), \
          "=r"((r)[24]),"=r"((r)[25]),"=r"((r)[26]),"=r"((r)[27]),"=r"((r)[28]),"=r"((r)[29]),"=r"((r)[30]),"=r"((r)[31]) \
        : "r"(a))

__device__ __forceinline__ u64 smem_desc(u32 addr) {
    const u64 base = (u64(2) << 61) | (u64(1) << 46) | (u64(64) << 32) | (u64(1) << 16);
    return base | ((u64)(addr >> 4) & 0x3FFF);
}
__device__ __forceinline__ u32 sw128(u32 off) { return off ^ ((off >> 3) & 0x70); }

#define IDESC_256 ((1u<<4) | (1u<<7) | (1u<<10) | ((256u/8)<<17) | ((128u/16)<<24))

// gemm1 smem (4 stages): full mbars @16..79; done @80..143;
// A(s) @1024 (16KB); B(s) @66560 (32KB). total 198656.
#define MB_FULL(s) (16 + (s) * 16)
#define MB_DONE(s) (80 + (s) * 16)
#define SM_A(s)  (1024 + (s) * 16384)
#define SM_B(s)  (66560 + (s) * 32768)
#define SM_TOTAL 198656
#define STAGE_BYTES 49152u

// gemm2 smem (128x512, 2 stages): A(s) @1024 (16KB ea), B(s) @33792 (64KB ea).
#define S2_A(s)  (1024 + (s) * 16384)
#define S2_B(s)  (33792 + (s) * 65536)
#define SM2_TOTAL 164864
#define STAGE2_BYTES 81920u

// ---------------------------------------------------------------------------
// prep kernels
// ---------------------------------------------------------------------------
__global__ void conv_x(const float* __restrict__ x) {
    int i = (blockIdx.x * 256 + threadIdx.x) * 4;
    float4 v = *(const float4*)(x + i);
    float f[4] = {v.x, v.y, v.z, v.w};
    #pragma unroll
    for (int k = 0; k < 4; k++) {
        bf16 h = __float2bfloat16(f[k]);
        g_xh[i + k]  = h;
        g_xlo[i + k] = __float2bfloat16(f[k] - __bfloat162float(h));
    }
}
__global__ void pack_V(const float* __restrict__ V) {
    int idx = blockIdx.x * 256 + threadIdx.x;
    int l = idx / VSEG, r = idx % VSEG;
    int n = r / 3072, kk = r % 3072;
    int seg = kk >> 10, k = kk & 1023;
    float v = V[(size_t)l * (Ee * Rr * Dd) + n * 1024 + k];
    bf16 h = __float2bfloat16(v);
    g_V2[idx] = (seg == 1) ? __float2bfloat16(v - __bfloat162float(h)) : h;
}
__global__ void pack_U(const float* __restrict__ U) {
    int idx = blockIdx.x * 256 + threadIdx.x;
    int l = idx / USEG, r = idx % USEG;
    int n = r / 768, kk = r % 768;
    int seg = kk >> 8, k = kk & 255;
    int e = k >> 6, rr = k & 63;
    float v = U[(size_t)l * (Ee * Rr * Dd) + e * (Dd * Rr) + n * Rr + rr];
    bf16 h = __float2bfloat16(v);
    g_U2[idx] = (seg == 1) ? __float2bfloat16(v - __bfloat162float(h)) : h;
}

// ---------------------------------------------------------------------------
// GEMM1 (round-15 verbatim): 4-stage TMA, tile 128x256, grid 128
// ---------------------------------------------------------------------------
__global__ void __launch_bounds__(256, 1)
gemm1_tc(const __grid_constant__ CUtensorMap mAh,
         const __grid_constant__ CUtensorMap mAl,
         const __grid_constant__ CUtensorMap mB,
         int layer) {
#if TC_OK
    extern __shared__ char smem[];
    const u32 sb = smem_u32(smem);
    const int tid = threadIdx.x, wid = tid >> 5, lane = tid & 31;
    const int m0 = blockIdx.x * 128;
    const int T = 48;

    if (wid == 0) TC_ALLOC(sb, 256);
    if (tid == 0) {
        #pragma unroll
        for (int s = 0; s < 4; s++) { MBAR_INIT(sb + MB_FULL(s), 1); MBAR_INIT(sb + MB_DONE(s), 1); }
        FENCE_ASYNC();
    }
    __syncthreads();
    u32 tmem;
    asm volatile("ld.shared.b32 %0, [%1];" : "=r"(tmem) : "r"(sb));

    if (tid == 0) {
        u32 fullph[4] = {0, 0, 0, 0}, doneph[4] = {0, 0, 0, 0};
        auto issue_load = [&](int t, int s) {
            MBAR_EXPECT_TX(sb + MB_FULL(s), STAGE_BYTES);
            const CUtensorMap* am = ((t >> 4) < 2) ? &mAh : &mAl;
            TMA2D(sb + SM_A(s), am, (t & 15) << 6, m0, sb + MB_FULL(s));
            TMA3D(sb + SM_B(s), &mB, t << 6, 0, layer, sb + MB_FULL(s));
        };
        issue_load(0, 0); issue_load(1, 1); issue_load(2, 2);

        #pragma unroll 1
        for (int t = 0; t < T; t++) {
            const int s = t & 3;
            mbar_wait(sb + MB_FULL(s), fullph[s]); fullph[s] ^= 1;
            u64 ad = smem_desc(sb + SM_A(s));
            u64 bd = smem_desc(sb + SM_B(s));
            #pragma unroll
            for (int k = 0; k < 4; k++)
                mma_f16_ss(tmem, ad + k * 2, bd + k * 2, IDESC_256, (t > 0) || (k > 0));
            TC_COMMIT(sb + MB_DONE(s));
            const int nt = t + 3;
            if (nt < T) {
                const int sl = nt & 3;
                if (t >= 1) { mbar_wait(sb + MB_DONE(sl), doneph[sl]); doneph[sl] ^= 1; }
                issue_load(nt, sl);
            }
        }
        #pragma unroll
        for (int s = 0; s < 4; s++) mbar_wait(sb + MB_DONE(s), doneph[s]);
    }
    __syncthreads();
    TC_FENCE_AFTER();

    const int sp = wid & 3;
    const int cbase = (wid >> 2) * 128;
    float* Tb = (float*)(smem + 1024) + wid * 1056;
    #pragma unroll 1
    for (int j = 0; j < 4; j++) {
        const int cb = cbase + j * 32;
        u32 r[32];
        LDTM32(r, tmem + cb);
        TC_WAIT_LD();
        #pragma unroll
        for (int c = 0; c < 32; c++) Tb[lane * 33 + c] = tanhf(__uint_as_float(r[c]));
        __syncwarp();
        #pragma unroll
        for (int rr = 0; rr < 32; rr++)
            g_t1[(size_t)(m0 + sp * 32 + rr) * ER + cb + lane] = Tb[rr * 33 + lane];
        __syncwarp();
    }
    __syncthreads();
    if (wid == 0) TC_DEALLOC(tmem, 256);
#else
    const int tid = threadIdx.x;
    const int m0 = blockIdx.x * 128;
    const bf16* Vb = g_V2 + (size_t)layer * VSEG;
    for (int o = tid; o < 128 * 256; o += 256) {
        int row = o >> 8, col = o & 255;
        const bf16* xh = g_xh  + (size_t)(m0 + row) * Dd;
        const bf16* xo = g_xlo + (size_t)(m0 + row) * Dd;
        const bf16* bv = Vb + (size_t)col * 3072;
        float acc = 0.f;
        for (int k = 0; k < Dd; k++) {
            float bh = __bfloat162float(bv[k]);
            float bl = __bfloat162float(bv[1024 + k]);
            acc += __bfloat162float(xh[k]) * (bh + bl) + __bfloat162float(xo[k]) * bh;
        }
        g_t1[(size_t)(m0 + row) * ER + col] = tanhf(acc);
    }
#endif
}

// ---------------------------------------------------------------------------
// gate_mix (round-10 verbatim)
// ---------------------------------------------------------------------------
#define CSTR 65
__global__ __launch_bounds__(256)
void gate_mix(const float* __restrict__ xl,
              const float* __restrict__ Cw,
              const float* __restrict__ gw)
{
    extern __shared__ float sm[];
    float* Cs  = sm;
    float* t1s = sm + 4 * Rr * CSTR;

    const int tid = threadIdx.x;
    for (int idx = tid; idx < Ee * Rr * Rr; idx += 256) {
        int e = idx >> 12, rem = idx & 4095, r = rem >> 6, s = rem & 63;
        Cs[(e * Rr + r) * CSTR + s] = Cw[idx];
    }
    const int b0 = blockIdx.x << 5;
    for (int idx = tid; idx < 32 * 256; idx += 256) {
        int rl = idx >> 8, j = idx & 255;
        t1s[idx] = g_t1[(size_t)(b0 + rl) * ER + j];
    }
    __syncthreads();

    const int w = tid >> 5, lane = tid & 31;
    #pragma unroll 1
    for (int q = 0; q < 4; q++) {
        const int rl = (w << 2) + q;
        const int b = b0 + rl;
        const float* xr = xl + (size_t)b * Dd;

        float s0 = 0.f, s1 = 0.f, s2 = 0.f, s3 = 0.f;
        for (int d = lane; d < Dd; d += 32) {
            float xv = xr[d];
            s0 = fmaf(xv, gw[d],          s0);
            s1 = fmaf(xv, gw[Dd + d],     s1);
            s2 = fmaf(xv, gw[2 * Dd + d], s2);
            s3 = fmaf(xv, gw[3 * Dd + d], s3);
        }
        #pragma unroll
        for (int o = 16; o; o >>= 1) {
            s0 += __shfl_xor_sync(0xffffffffu, s0, o);
            s1 += __shfl_xor_sync(0xffffffffu, s1, o);
            s2 += __shfl_xor_sync(0xffffffffu, s2, o);
            s3 += __shfl_xor_sync(0xffffffffu, s3, o);
        }
        float mx = fmaxf(fmaxf(s0, s1), fmaxf(s2, s3));
        float e0 = expf(s0 - mx), e1 = expf(s1 - mx), e2 = expf(s2 - mx), e3 = expf(s3 - mx);
        float inv = 1.f / (e0 + e1 + e2 + e3);
        float gg[4] = { e0 * inv, e1 * inv, e2 * inv, e3 * inv };

        const float* t1r = t1s + rl * ER;
        #pragma unroll
        for (int i = 0; i < 8; i++) {
            int j = (i << 5) + lane;
            int e = j >> 6, r = j & 63;
            const float* cr = Cs + (e * Rr + r) * CSTR;
            const float* tv = t1r + (e << 6);
            float sum = 0.f;
            #pragma unroll
            for (int s = 0; s < 64; s++) sum = fmaf(cr[s], tv[s], sum);
            float val = gg[e] * tanhf(sum);
            bf16 h = __float2bfloat16(val);
            size_t o = (size_t)b * ER + j;
            g_sh[o] = h;
            g_sl[o] = __float2bfloat16(val - __bfloat162float(h));
        }
    }
}

// ---------------------------------------------------------------------------
// GEMM2 (round-15 mainloop verbatim): tile 128x512, grid (2,128).
// Epilogue rewritten with vector memory ops: lane = (row-group, 4-col span);
// STG.128 out + 8B packed bf16 stores; LDG.128 xl/x0. Same per-element math.
// ---------------------------------------------------------------------------
__global__ void __launch_bounds__(256, 1)
gemm2_tc(const __grid_constant__ CUtensorMap mSh,
         const __grid_constant__ CUtensorMap mSl,
         const __grid_constant__ CUtensorMap mU,
         const float* __restrict__ xl_in,
         const float* __restrict__ x0,
         const float* __restrict__ bias,
         float* __restrict__ out,
         int write_next, int layer)
{
#if TC_OK
    extern __shared__ char smem[];
    const u32 sb = smem_u32(smem);
    const int tid = threadIdx.x, wid = tid >> 5, lane = tid & 31;
    const int n0 = blockIdx.x * 512;
    const int m0 = blockIdx.y * 128;
    const int T = 12;

    if (wid == 0) TC_ALLOC(sb, 512);
    if (tid == 0) {
        #pragma unroll
        for (int s = 0; s < 2; s++) { MBAR_INIT(sb + MB_FULL(s), 1); MBAR_INIT(sb + MB_DONE(s), 1); }
        FENCE_ASYNC();
    }
    __syncthreads();
    u32 tmem;
    asm volatile("ld.shared.b32 %0, [%1];" : "=r"(tmem) : "r"(sb));

    if (tid == 0) {
        u32 fullph[2] = {0, 0}, doneph[2] = {0, 0};
        auto issue_load = [&](int t, int s) {
            MBAR_EXPECT_TX(sb + MB_FULL(s), STAGE2_BYTES);
            const CUtensorMap* am = ((t >> 2) < 2) ? &mSh : &mSl;
            TMA2D(sb + S2_A(s), am, (t & 3) << 6, m0, sb + MB_FULL(s));
            TMA3D(sb + S2_B(s),         &mU, t << 6, n0,       layer, sb + MB_FULL(s));
            TMA3D(sb + S2_B(s) + 32768, &mU, t << 6, n0 + 256, layer, sb + MB_FULL(s));
        };
        issue_load(0, 0); issue_load(1, 1);

        #pragma unroll 1
        for (int t = 0; t < T; t++) {
            const int s = t & 1;
            mbar_wait(sb + MB_FULL(s), fullph[s]); fullph[s] ^= 1;
            u64 ad  = smem_desc(sb + S2_A(s));
            u64 bd  = smem_desc(sb + S2_B(s));
            u64 bd2 = smem_desc(sb + S2_B(s) + 32768);
            #pragma unroll
            for (int k = 0; k < 4; k++) {
                u32 acc = (t > 0) || (k > 0);
                mma_f16_ss(tmem,       ad + k * 2, bd  + k * 2, IDESC_256, acc);
                mma_f16_ss(tmem + 256, ad + k * 2, bd2 + k * 2, IDESC_256, acc);
            }
            TC_COMMIT(sb + MB_DONE(s));
            const int nt = t + 2;
            if (nt < T) {
                mbar_wait(sb + MB_DONE(s), doneph[s]); doneph[s] ^= 1;
                issue_load(nt, s);
            }
        }
        #pragma unroll
        for (int s = 0; s < 2; s++) mbar_wait(sb + MB_DONE(s), doneph[s]);
    }
    __syncthreads();
    TC_FENCE_AFTER();

    // epilogue: per chunk, transpose (stride 36 -> 16B-aligned float4 rows),
    // then lane = (g = lane>>3 row-in-group, li = lane&7 4-col span): per
    // 4-row block one float4 out store + two 8B bf16 stores, float4 loads.
    const int sp = wid & 3;
    const int cbase = (wid >> 2) * 256;
    const int g  = lane >> 3, li = lane & 7;
    float* Tb = (float*)(smem + 1024) + wid * 1152;   // 32x36
    #pragma unroll 1
    for (int j = 0; j < 8; j++) {
        const int cb = cbase + j * 32;
        u32 r[32];
        LDTM32(r, tmem + cb);                 // async until wait::ld
        const int col0 = n0 + cb + li * 4;
        float4 bv = *(const float4*)(bias + col0);
        float4 xv[8], xx[8];                  // overlap global loads with LDTM
        #pragma unroll
        for (int rb = 0; rb < 8; rb++) {
            const int row = rb * 4 + g;
            const size_t idx = (size_t)(m0 + sp * 32 + row) * Dd + col0;
            xv[rb] = *(const float4*)(xl_in + idx);
            xx[rb] = *(const float4*)(x0 + idx);
        }
        TC_WAIT_LD();
        #pragma unroll
        for (int c = 0; c < 32; c++) Tb[lane * 36 + c] = __uint_as_float(r[c]);
        __syncwarp();
        #pragma unroll
        for (int rb = 0; rb < 8; rb++) {
            const int row = rb * 4 + g;
            const size_t idx = (size_t)(m0 + sp * 32 + row) * Dd + col0;
            float4 t = *(const float4*)(&Tb[row * 36 + li * 4]);
            float4 o;
            o.x = fmaf(xx[rb].x, bv.x + t.x, xv[rb].x);
            o.y = fmaf(xx[rb].y, bv.y + t.y, xv[rb].y);
            o.z = fmaf(xx[rb].z, bv.z + t.z, xv[rb].z);
            o.w = fmaf(xx[rb].w, bv.w + t.w, xv[rb].w);
            *(float4*)(out + idx) = o;
            if (write_next) {
                bf16 h0 = __float2bfloat16(o.x), h1 = __float2bfloat16(o.y);
                bf16 h2 = __float2bfloat16(o.z), h3 = __float2bfloat16(o.w);
                uint2 hp;
                hp.x = ((u32)__bfloat16_as_ushort(h1) << 16) | __bfloat16_as_ushort(h0);
                hp.y = ((u32)__bfloat16_as_ushort(h3) << 16) | __bfloat16_as_ushort(h2);
                *(uint2*)(g_xh + idx) = hp;
                bf16 l0 = __float2bfloat16(o.x - __bfloat162float(h0));
                bf16 l1 = __float2bfloat16(o.y - __bfloat162float(h1));
                bf16 l2 = __float2bfloat16(o.z - __bfloat162float(h2));
                bf16 l3 = __float2bfloat16(o.w - __bfloat162float(h3));
                uint2 lp;
                lp.x = ((u32)__bfloat16_as_ushort(l1) << 16) | __bfloat16_as_ushort(l0);
                lp.y = ((u32)__bfloat16_as_ushort(l3) << 16) | __bfloat16_as_ushort(l2);
                *(uint2*)(g_xlo + idx) = lp;
            }
        }
        __syncwarp();
    }
    __syncthreads();
    if (wid == 0) TC_DEALLOC(tmem, 512);
#else
    const int tid = threadIdx.x;
    const int n0 = blockIdx.x * 512;
    const int m0 = blockIdx.y * 128;
    const bf16* Ub = g_U2 + (size_t)layer * USEG;
    for (int o = tid; o < 128 * 512; o += 256) {
        int row = o >> 9, cl = o & 511;
        int col = n0 + cl;
        const bf16* sh = g_sh + (size_t)(m0 + row) * ER;
        const bf16* sl = g_sl + (size_t)(m0 + row) * ER;
        const bf16* uv = Ub + (size_t)col * 768;
        float acc = 0.f;
        for (int k = 0; k < ER; k++) {
            float uh = __bfloat162float(uv[k]);
            float ul = __bfloat162float(uv[256 + k]);
            acc += __bfloat162float(sh[k]) * (uh + ul) + __bfloat162float(sl[k]) * uh;
        }
        const size_t idx = (size_t)(m0 + row) * Dd + col;
        float ov = fmaf(x0[idx], bias[col] + acc, xl_in[idx]);
        out[idx] = ov;
        if (write_next) {
            bf16 h = __float2bfloat16(ov);
            g_xh[idx]  = h;
            g_xlo[idx] = __float2bfloat16(ov - __bfloat162float(h));
        }
    }
#endif
}

// ---------------------------------------------------------------------------
// Launch
// ---------------------------------------------------------------------------
typedef CUresult (CUDAAPI *PFN_encodeTiled)(
    CUtensorMap*, CUtensorMapDataType, cuuint32_t, void*,
    const cuuint64_t*, const cuuint64_t*, const cuuint32_t*, const cuuint32_t*,
    CUtensorMapInterleave, CUtensorMapSwizzle, CUtensorMapL2promotion, CUtensorMapFloatOOBfill);

extern "C" void kernel_launch(void* const* d_in, const int* in_sizes, int n_in,
                              void* d_out, int out_size)
{
    const float* x    = (const float*)d_in[0];
    const float* U    = (const float*)d_in[1];
    const float* V    = (const float*)d_in[2];
    const float* C    = (const float*)d_in[3];
    const float* bias = (const float*)d_in[4];
    const float* gw   = (const float*)d_in[5];
    float* out = (float*)d_out;

    float* p_xl = nullptr;
    cudaGetSymbolAddress((void**)&p_xl, g_xl);
    void *p_xh, *p_xlo, *p_sh, *p_sl, *p_V2, *p_U2;
    cudaGetSymbolAddress(&p_xh,  g_xh);
    cudaGetSymbolAddress(&p_xlo, g_xlo);
    cudaGetSymbolAddress(&p_sh,  g_sh);
    cudaGetSymbolAddress(&p_sl,  g_sl);
    cudaGetSymbolAddress(&p_V2,  g_V2);
    cudaGetSymbolAddress(&p_U2,  g_U2);

    static PFN_encodeTiled enc = nullptr;
    if (!enc) {
        cudaDriverEntryPointQueryResult st;
        cudaGetDriverEntryPoint("cuTensorMapEncodeTiled", (void**)&enc,
                                cudaEnableDefault, &st);
    }

    auto enc2d = [&](CUtensorMap* m, void* base, unsigned long long d0,
                     unsigned long long d1, unsigned b0, unsigned b1) {
        cuuint64_t dims[2] = {d0, d1};
        cuuint64_t strides[1] = {d0 * 2};
        cuuint32_t box[2] = {b0, b1};
        cuuint32_t es[2] = {1, 1};
        enc(m, CU_TENSOR_MAP_DATA_TYPE_BFLOAT16, 2, base, dims, strides, box, es,
            CU_TENSOR_MAP_INTERLEAVE_NONE, CU_TENSOR_MAP_SWIZZLE_128B,
            CU_TENSOR_MAP_L2_PROMOTION_L2_128B, CU_TENSOR_MAP_FLOAT_OOB_FILL_NONE);
    };
    auto enc3d = [&](CUtensorMap* m, void* base, unsigned long long d0,
                     unsigned long long d1, unsigned long long d2,
                     unsigned b0, unsigned b1) {
        cuuint64_t dims[3] = {d0, d1, d2};
        cuuint64_t strides[2] = {d0 * 2, d0 * d1 * 2};
        cuuint32_t box[3] = {b0, b1, 1};
        cuuint32_t es[3] = {1, 1, 1};
        enc(m, CU_TENSOR_MAP_DATA_TYPE_BFLOAT16, 3, base, dims, strides, box, es,
            CU_TENSOR_MAP_INTERLEAVE_NONE, CU_TENSOR_MAP_SWIZZLE_128B,
            CU_TENSOR_MAP_L2_PROMOTION_L2_128B, CU_TENSOR_MAP_FLOAT_OOB_FILL_NONE);
    };

    CUtensorMap mAh{}, mAl{}, mV{}, mSh{}, mSl{}, mU{};
    enc2d(&mAh, p_xh,  1024, 16384, 64, 128);
    enc2d(&mAl, p_xlo, 1024, 16384, 64, 128);
    enc3d(&mV,  p_V2,  3072, 256, 3, 64, 256);
    enc2d(&mSh, p_sh,  256, 16384, 64, 128);
    enc2d(&mSl, p_sl,  256, 16384, 64, 128);
    enc3d(&mU,  p_U2,  768, 1024, 3, 64, 256);

    const int smem_gate = (4 * Rr * CSTR + 32 * 256) * (int)sizeof(float); // 99328
    cudaFuncSetAttribute(gate_mix, cudaFuncAttributeMaxDynamicSharedMemorySize, smem_gate);
    cudaFuncSetAttribute(gemm1_tc, cudaFuncAttributeMaxDynamicSharedMemorySize, SM_TOTAL);
    cudaFuncSetAttribute(gemm2_tc, cudaFuncAttributeMaxDynamicSharedMemorySize, SM2_TOTAL);

    conv_x<<<Bsz * Dd / 1024, 256>>>(x);
    pack_V<<<Ll * VSEG / 256, 256>>>(V);
    pack_U<<<Ll * USEG / 256, 256>>>(U);

    for (int l = 0; l < Ll; l++) {
        const float* xin  = (l == 0)      ? x   : p_xl;
        float*       xout = (l == Ll - 1) ? out : p_xl;
        gemm1_tc<<<Bsz / 128, 256, SM_TOTAL>>>(mAh, mAl, mV, l);
        gate_mix<<<Bsz / 32, 256, smem_gate>>>(xin, C + (size_t)l * Ee * Rr * Rr, gw);
        gemm2_tc<<<dim3(2, 128), 256, SM2_TOTAL>>>(mSh, mSl, mU, xin, x,
                                                   bias + (size_t)l * Dd, xout,
                                                   (l < Ll - 1) ? 1 : 0, l);
    }
}